// round 14
// baseline (speedup 1.0000x reference)
#include <cuda_runtime.h>
#include <cuda_fp16.h>
#include <cstdint>
#include <math.h>

// Problem constants
#define NB 2
#define NC 64
#define CI 32
#define NH 128
#define NW 128
#define NBQ 8      // b*4+q
#define NN 4096    // 64*64 spatial per quadrant
#define HW (NH*NW)
#define NT 32      // key tiles of 128
#define LOG2E 1.4426950408889634f
#define YS_BLOCKS 32   // ystats blocks per quadrant

// Scratch (static device globals; allocation-free)
__device__ __align__(128) __half g_th [NBQ * NN * CI];   // theta*log2e [bq][n][d] fp16
__device__ __align__(128) __half g_ph [NBQ * NN * CI];   // phi   [bq][m][d] fp16
__device__ __align__(128) __half g_gxT[NBQ * CI * NN];   // g^T   [bq][d][m] fp16
__device__ __align__(128) float  g_y  [NBQ * NN * CI];   // attn out [bq][n][d] fp32
__device__ __align__(128) float  g_part[4 * YS_BLOCKS * 1056]; // per-block {sum_y[32], M[32][32]}
__device__ float g_mu[4 * NC];     // d = w_c . mean(y)  (bias cancels in BN)
__device__ float g_rstd[4 * NC];

// ===========================================================================
// PTX helpers (all legal on compute_103)
// ===========================================================================
__device__ __forceinline__ uint32_t smem_to_u32(const void* p) {
    uint32_t a;
    asm("{ .reg .u64 t; cvta.to.shared.u64 t, %1; cvt.u32.u64 %0, t; }" : "=r"(a) : "l"(p));
    return a;
}
__device__ __forceinline__ void cp16(uint32_t s, const void* g) {
    asm volatile("cp.async.cg.shared.global [%0], [%1], 16;" :: "r"(s), "l"(g));
}
#define CP_COMMIT() asm volatile("cp.async.commit_group;" ::: "memory")
#define CP_WAIT(n)  asm volatile("cp.async.wait_group %0;" :: "n"(n) : "memory")

// 2^x on packed f16x2
__device__ __forceinline__ uint32_t ex2h2(uint32_t x) {
    uint32_t r;
    asm("ex2.approx.f16x2 %0, %1;" : "=r"(r) : "r"(x));
    return r;
}

// f32-accum MMA (for P.V)
__device__ __forceinline__ void mma_f16(float& c0, float& c1, float& c2, float& c3,
                                        uint32_t a0, uint32_t a1, uint32_t a2, uint32_t a3,
                                        uint32_t b0, uint32_t b1) {
    asm volatile(
        "mma.sync.aligned.m16n8k16.row.col.f32.f16.f16.f32 "
        "{%0,%1,%2,%3}, {%4,%5,%6,%7}, {%8,%9}, {%0,%1,%2,%3};"
        : "+f"(c0), "+f"(c1), "+f"(c2), "+f"(c3)
        : "r"(a0), "r"(a1), "r"(a2), "r"(a3), "r"(b0), "r"(b1));
}
// f16-accum MMA (for S = theta.phi^T) — D comes out pre-packed for ex2h2
__device__ __forceinline__ void mma_f16h(uint32_t& d0, uint32_t& d1,
                                         uint32_t a0, uint32_t a1, uint32_t a2, uint32_t a3,
                                         uint32_t b0, uint32_t b1) {
    asm volatile(
        "mma.sync.aligned.m16n8k16.row.col.f16.f16.f16.f16 "
        "{%0,%1}, {%2,%3,%4,%5}, {%6,%7}, {%0,%1};"
        : "+r"(d0), "+r"(d1)
        : "r"(a0), "r"(a1), "r"(a2), "r"(a3), "r"(b0), "r"(b1));
}

// ===========================================================================
// Kernel A: projections (split per-matrix; proven R8 version).
// theta pre-scaled by log2(e); g written transposed fp16 [d][m].
// ===========================================================================
__global__ __launch_bounds__(128) void proj_kernel(
    const float* __restrict__ x,
    const float* __restrict__ tw, const float* __restrict__ tb,
    const float* __restrict__ pw, const float* __restrict__ pb,
    const float* __restrict__ gw, const float* __restrict__ gb)
{
    __shared__ __align__(16) float ws[NC * CI];
    __shared__ float bs[CI];

    int mat = blockIdx.y;
    const float* W  = (mat == 0) ? tw : ((mat == 1) ? pw : gw);
    const float* Bv = (mat == 0) ? tb : ((mat == 1) ? pb : gb);
    float scale = (mat == 0) ? LOG2E : 1.0f;

    int tid = threadIdx.x;
    for (int i = tid; i < CI * NC; i += 128) {
        int o = i >> 6, c = i & 63;
        ws[c * CI + o] = W[i] * scale;
    }
    if (tid < CI) bs[tid] = Bv[tid] * scale;
    __syncthreads();

    int bq = blockIdx.z;
    int n  = blockIdx.x * 128 + tid;
    int b  = bq >> 2, q = bq & 3, qr = q >> 1, qc = q & 1;
    int hh = n >> 6, ww = n & 63;

    const float* xp = x + (size_t)b * NC * HW + (qr * 64 + hh) * NW + (qc * 64 + ww);

    float acc[CI];
#pragma unroll
    for (int o = 0; o < CI; o++) acc[o] = bs[o];

    const float4* ws4 = (const float4*)ws;
#pragma unroll 4
    for (int c = 0; c < NC; c++) {
        float xv = xp[c * HW];
#pragma unroll
        for (int o4 = 0; o4 < 8; o4++) {
            float4 w = ws4[c * 8 + o4];
            acc[o4 * 4 + 0] += w.x * xv;
            acc[o4 * 4 + 1] += w.y * xv;
            acc[o4 * 4 + 2] += w.z * xv;
            acc[o4 * 4 + 3] += w.w * xv;
        }
    }

    if (mat == 2) {
        __half* op = g_gxT + (size_t)bq * CI * NN + n;
#pragma unroll
        for (int o = 0; o < CI; o++) op[(size_t)o * NN] = __float2half_rn(acc[o]);
    } else {
        __half* op = ((mat == 0) ? g_th : g_ph) + ((size_t)bq * NN + n) * CI;
#pragma unroll
        for (int o = 0; o < CI; o += 2) {
            __half2 h2 = __floats2half2_rn(acc[o], acc[o + 1]);
            *(__half2*)(op + o) = h2;
        }
    }
}

// ===========================================================================
// Kernel B: fp16 flash attention — BIT-IDENTICAL to R12 best (98.8us).
// M=32 rows per warp, 4-warp CTAs, grid (32, 8), block 128.
// ===========================================================================
#define PH2 20                         // phi row stride in b32 words (16 data + 4 pad)
#define VT2 68                         // v^T row stride in b32 words (64 data + 4 pad)
#define PHI_WORDS (128 * PH2)          // 2560
#define VT_WORDS  (32 * VT2)           // 2176
#define BUF_WORDS (PHI_WORDS + VT_WORDS)  // 4736
#define PHI_BYTES (PHI_WORDS * 4)
#define BUF_BYTES (BUF_WORDS * 4)      // 18944
#define SMEM_TOTAL (2 * BUF_BYTES)     // 37888

__global__ void __launch_bounds__(128, 2) attn_mma_kernel()
{
    extern __shared__ uint32_t smw[];
    uint32_t sb = smem_to_u32(smw);
    int tid = threadIdx.x, wid = tid >> 5, lane = tid & 31;
    int g = lane >> 2, tig = lane & 3;               // row-group, thread-in-group
    int bq = blockIdx.y, qt = blockIdx.x;

    const __half* phg = g_ph  + (size_t)bq * NN * CI;
    const __half* vtg = g_gxT + (size_t)bq * CI * NN;

    // ---- theta A fragments: two 16-row groups (rows qt*128 + wid*32 + grp*16) ----
    uint32_t aS[2][2][4];
#pragma unroll
    for (int grp = 0; grp < 2; grp++) {
        const __half* thp = g_th + ((size_t)bq * NN + qt * 128 + wid * 32 + grp * 16) * CI;
#pragma unroll
        for (int kk = 0; kk < 2; kk++) {
            aS[grp][kk][0] = *(const uint32_t*)(thp + (size_t)g       * CI + (tig + 8 * kk) * 2);
            aS[grp][kk][1] = *(const uint32_t*)(thp + (size_t)(g + 8) * CI + (tig + 8 * kk) * 2);
            aS[grp][kk][2] = *(const uint32_t*)(thp + (size_t)g       * CI + (tig + 4 + 8 * kk) * 2);
            aS[grp][kk][3] = *(const uint32_t*)(thp + (size_t)(g + 8) * CI + (tig + 4 + 8 * kk) * 2);
        }
    }

    // ---- stage helper: tile t -> buffer buf (phi rows + v^T rows), cp.async ----
    auto stage = [&](int t, int buf) {
        uint32_t base = sb + (uint32_t)buf * BUF_BYTES;
        const __half* pg = phg + (size_t)t * 128 * CI;
#pragma unroll
        for (int cc = 0; cc < 4; cc++) {
            int idx = tid + cc * 128;            // 0..511
            int row = idx >> 2, ch = idx & 3;    // phi: 128 rows x 4 chunks of 16B
            cp16(base + (uint32_t)(row * PH2 + ch * 4) * 4u, pg + (size_t)row * CI + ch * 8);
            int d = idx >> 4, kc = idx & 15;     // v^T: 32 rows x 16 chunks of 16B
            cp16(base + PHI_BYTES + (uint32_t)(d * VT2 + kc * 4) * 4u,
                 vtg + (size_t)d * NN + t * 128 + kc * 8);
        }
    };

    stage(0, 0);
    CP_COMMIT();

    float o[2][4][4];
#pragma unroll
    for (int grp = 0; grp < 2; grp++)
#pragma unroll
        for (int d = 0; d < 4; d++)
#pragma unroll
            for (int j = 0; j < 4; j++) o[grp][d][j] = 0.0f;
    float ls[2][2] = {{0.0f, 0.0f}, {0.0f, 0.0f}};

    for (int t = 0; t < NT; t++) {
        int cur = t & 1;
        if (t + 1 < NT) {
            stage(t + 1, cur ^ 1);
            CP_COMMIT();
            CP_WAIT(1);
        } else {
            CP_WAIT(0);
        }
        __syncthreads();

        const uint32_t* psw = smw + (size_t)cur * BUF_WORDS;
        const uint32_t* vtw = psw + PHI_WORDS;

#pragma unroll
        for (int nbp = 0; nbp < 8; nbp++) {
            const uint32_t* prow0 = psw + (nbp * 16 + g) * PH2;
            const uint32_t* prow1 = psw + (nbp * 16 + 8 + g) * PH2;
            uint32_t p00 = prow0[tig], p01 = prow0[tig + 4];
            uint32_t p02 = prow0[tig + 8], p03 = prow0[tig + 12];
            uint32_t p10 = prow1[tig], p11 = prow1[tig + 4];
            uint32_t p12 = prow1[tig + 8], p13 = prow1[tig + 12];

            uint32_t A[2][4];
#pragma unroll
            for (int grp = 0; grp < 2; grp++) {
                uint32_t s0 = 0, s1 = 0;
                mma_f16h(s0, s1, aS[grp][0][0], aS[grp][0][1], aS[grp][0][2], aS[grp][0][3],
                         p00, p01);
                mma_f16h(s0, s1, aS[grp][1][0], aS[grp][1][1], aS[grp][1][2], aS[grp][1][3],
                         p02, p03);
                uint32_t u0 = 0, u1 = 0;
                mma_f16h(u0, u1, aS[grp][0][0], aS[grp][0][1], aS[grp][0][2], aS[grp][0][3],
                         p10, p11);
                mma_f16h(u0, u1, aS[grp][1][0], aS[grp][1][1], aS[grp][1][2], aS[grp][1][3],
                         p12, p13);
                A[grp][0] = ex2h2(s0);
                A[grp][1] = ex2h2(s1);
                A[grp][2] = ex2h2(u0);
                A[grp][3] = ex2h2(u1);
                __half2 hg = __hadd2(*(__half2*)&A[grp][0], *(__half2*)&A[grp][2]);
                __half2 hb = __hadd2(*(__half2*)&A[grp][1], *(__half2*)&A[grp][3]);
                float2 fg = __half22float2(hg);
                float2 fb = __half22float2(hb);
                ls[grp][0] += fg.x + fg.y;
                ls[grp][1] += fb.x + fb.y;
            }
#pragma unroll
            for (int d = 0; d < 4; d++) {
                const uint32_t* v = vtw + (g + 8 * d) * VT2 + nbp * 8;
                uint32_t vb0 = v[tig], vb1 = v[tig + 4];
                mma_f16(o[0][d][0], o[0][d][1], o[0][d][2], o[0][d][3],
                        A[0][0], A[0][1], A[0][2], A[0][3], vb0, vb1);
                mma_f16(o[1][d][0], o[1][d][1], o[1][d][2], o[1][d][3],
                        A[1][0], A[1][1], A[1][2], A[1][3], vb0, vb1);
            }
        }
        __syncthreads();
    }

#pragma unroll
    for (int grp = 0; grp < 2; grp++) {
        float l0 = ls[grp][0], l1 = ls[grp][1];
        l0 += __shfl_xor_sync(0xFFFFFFFFu, l0, 1);
        l0 += __shfl_xor_sync(0xFFFFFFFFu, l0, 2);
        l1 += __shfl_xor_sync(0xFFFFFFFFu, l1, 1);
        l1 += __shfl_xor_sync(0xFFFFFFFFu, l1, 2);
        float inv0 = 1.0f / l0;
        float inv1 = 1.0f / l1;

        int row0 = qt * 128 + wid * 32 + grp * 16 + g;
        float* y0 = g_y + ((size_t)bq * NN + row0) * CI;
        float* y1 = y0 + 8 * CI;
#pragma unroll
        for (int j = 0; j < 4; j++) {
            *(float2*)(y0 + j * 8 + 2 * tig) =
                make_float2(o[grp][j][0] * inv0, o[grp][j][1] * inv0);
            *(float2*)(y1 + j * 8 + 2 * tig) =
                make_float2(o[grp][j][2] * inv1, o[grp][j][3] * inv1);
        }
    }
}

// ===========================================================================
// Kernel Y: per-quadrant y-space moments: partial {sum_y[32], M=sum y y^T}
// grid (YS_BLOCKS, 4), block 256 (8 warps; 32 rows per warp)
// ===========================================================================
__global__ __launch_bounds__(256) void ystats_kernel()
{
    int q = blockIdx.y, blk = blockIdx.x;
    int tid = threadIdx.x, wid = tid >> 5, lane = tid & 31;

    float acc[CI];
#pragma unroll
    for (int i = 0; i < CI; i++) acc[i] = 0.0f;
    float s = 0.0f;

    int rbase = blk * 256 + wid * 32;   // rows 0..8191 per quadrant (b-major)
    for (int r = 0; r < 32; r++) {
        int row = rbase + r;
        int b = row >> 12, n = row & 4095;
        const float* yp = g_y + (((size_t)(b * 4 + q) * NN) + n) * CI;
        float v = yp[lane];
        s += v;
#pragma unroll
        for (int i = 0; i < CI; i++) {
            float yi = __shfl_sync(0xFFFFFFFFu, v, i);
            acc[i] += yi * v;           // lane j accumulates M[i][j]
        }
    }

    __shared__ float smM[8 * 1024];
    __shared__ float smS[8 * 32];
#pragma unroll
    for (int i = 0; i < CI; i++) smM[wid * 1024 + i * 32 + lane] = acc[i];
    smS[wid * 32 + lane] = s;
    __syncthreads();

    float* part = g_part + ((size_t)q * YS_BLOCKS + blk) * 1056;
    for (int i = tid; i < 1024; i += 256) {
        float t = 0.0f;
#pragma unroll
        for (int w = 0; w < 8; w++) t += smM[w * 1024 + i];
        part[32 + i] = t;
    }
    if (tid < 32) {
        float t = 0.0f;
#pragma unroll
        for (int w = 0; w < 8; w++) t += smS[w * 32 + tid];
        part[tid] = t;
    }
}

// ===========================================================================
// Kernel M: reduce partials; per (q,c): d = w.m ; var = (w^T M w)/N - d^2
// grid 4 (quadrant), block 256
// ===========================================================================
__global__ __launch_bounds__(256) void musigma_kernel(const float* __restrict__ w_w)
{
    int q = blockIdx.x, tid = threadIdx.x;
    __shared__ float M[1024];
    __shared__ float sv[32];
    __shared__ float wsm[64 * 33];   // padded stride 33 (conflict-free)

    const float* pbase = g_part + (size_t)q * YS_BLOCKS * 1056;
    for (int i = tid; i < 1024; i += 256) {
        float t = 0.0f;
#pragma unroll 4
        for (int p = 0; p < YS_BLOCKS; p++) t += pbase[p * 1056 + 32 + i];
        M[i] = t;
    }
    if (tid < 32) {
        float t = 0.0f;
#pragma unroll 4
        for (int p = 0; p < YS_BLOCKS; p++) t += pbase[p * 1056 + tid];
        sv[tid] = t;
    }
    for (int i = tid; i < NC * CI; i += 256) wsm[(i >> 5) * 33 + (i & 31)] = w_w[i];
    __syncthreads();

    if (tid < NC) {
        int c = tid;
        const float* w = wsm + c * 33;
        float d = 0.0f;
#pragma unroll
        for (int i = 0; i < CI; i++) d += w[i] * sv[i];
        d *= (1.0f / 8192.0f);
        float Q = 0.0f;
#pragma unroll 4
        for (int i = 0; i < CI; i++) {
            float ti = 0.0f;
#pragma unroll
            for (int j = 0; j < CI; j++) ti += M[i * 32 + j] * w[j];
            Q += w[i] * ti;
        }
        float var = Q * (1.0f / 8192.0f) - d * d;
        g_mu[q * NC + c]   = d;
        g_rstd[q * NC + c] = rsqrtf(var + 1e-5f);
    }
}

// ===========================================================================
// Kernel O: fused W-proj + BN + residual + scatter:
// out = (w_c.y_n - d_qc) * rstd_qc * gamma_c + beta_c + x   (bias cancels)
// grid (32 ntiles, 8 bq), block 256
// ===========================================================================
__global__ __launch_bounds__(256) void outf_kernel(
    const float* __restrict__ x, const float* __restrict__ w_w,
    const float* __restrict__ gamma, const float* __restrict__ beta,
    float* __restrict__ out)
{
    __shared__ __align__(16) float ys[128 * CI];
    __shared__ __align__(16) float wws[NC * CI];
    __shared__ float mus[NC], rss[NC], gas[NC], bes[NC];

    int bq = blockIdx.y, q = bq & 3, b = bq >> 2;
    int n0 = blockIdx.x * 128;
    int tid = threadIdx.x;

    for (int i = tid; i < NC * CI; i += 256) wws[i] = w_w[i];
    {
        const float4* src = (const float4*)(g_y + ((size_t)bq * NN + n0) * CI);
        float4* dst = (float4*)ys;
#pragma unroll
        for (int i = 0; i < 4; i++) dst[tid + i * 256] = src[tid + i * 256];
    }
    if (tid < NC) {
        mus[tid] = g_mu[q * NC + tid];
        rss[tid] = g_rstd[q * NC + tid];
        gas[tid] = gamma[tid];
        bes[tid] = beta[tid];
    }
    __syncthreads();

    int n = tid & 127;
    int chalf = (tid >> 7) * 32;

    float yr[CI];
#pragma unroll
    for (int o = 0; o < CI; o++) yr[o] = ys[n * CI + o];

    int nn = n0 + n;
    int hh = nn >> 6, wq = nn & 63;
    int h = (q >> 1) * 64 + hh, wcol = (q & 1) * 64 + wq;
    size_t xbase = ((size_t)b * NC) * HW + (size_t)h * NW + wcol;

    const float4* wws4 = (const float4*)wws;
    for (int cc = 0; cc < 32; cc++) {
        int c = chalf + cc;
        float a = 0.0f;
#pragma unroll
        for (int o4 = 0; o4 < 8; o4++) {
            float4 w = wws4[c * 8 + o4];
            a += w.x * yr[o4 * 4 + 0] + w.y * yr[o4 * 4 + 1]
               + w.z * yr[o4 * 4 + 2] + w.w * yr[o4 * 4 + 3];
        }
        size_t idx = xbase + (size_t)c * HW;
        out[idx] = (a - mus[c]) * rss[c] * gas[c] + bes[c] + x[idx];
    }
}

// ===========================================================================
// Launch
// ===========================================================================
extern "C" void kernel_launch(void* const* d_in, const int* in_sizes, int n_in,
                              void* d_out, int out_size)
{
    const float* x   = (const float*)d_in[0];
    const float* gw  = (const float*)d_in[1];
    const float* gb  = (const float*)d_in[2];
    const float* tw  = (const float*)d_in[3];
    const float* tb  = (const float*)d_in[4];
    const float* pw  = (const float*)d_in[5];
    const float* pb  = (const float*)d_in[6];
    const float* ww  = (const float*)d_in[7];
    const float* wb  = (const float*)d_in[8];   // cancels in BN; unused
    const float* bng = (const float*)d_in[9];
    const float* bnb = (const float*)d_in[10];
    float* out = (float*)d_out;
    (void)wb;

    cudaFuncSetAttribute(attn_mma_kernel,
                         cudaFuncAttributeMaxDynamicSharedMemorySize, SMEM_TOTAL);

    dim3 gA(32, 3, 8);
    proj_kernel<<<gA, 128>>>(x, tw, tb, pw, pb, gw, gb);

    dim3 gB(32, 8);
    attn_mma_kernel<<<gB, 128, SMEM_TOTAL>>>();

    dim3 gY(YS_BLOCKS, 4);
    ystats_kernel<<<gY, 256>>>();

    musigma_kernel<<<4, 256>>>(ww);

    dim3 gO(32, 8);
    outf_kernel<<<gO, 256>>>(x, ww, bng, bnb, out);
}

// round 15
// speedup vs baseline: 1.2755x; 1.2755x over previous
#include <cuda_runtime.h>
#include <cuda_fp16.h>
#include <cstdint>
#include <math.h>

// Problem constants
#define NB 2
#define NC 64
#define CI 32
#define NH 128
#define NW 128
#define NBQ 8      // b*4+q
#define NN 4096    // 64*64 spatial per quadrant
#define HW (NH*NW)
#define NT 32      // key tiles of 128
#define LOG2E 1.4426950408889634f

// Scratch (static device globals; allocation-free)
__device__ __align__(128) __half g_th [NBQ * NN * CI];   // theta*log2e [bq][n][d] fp16
__device__ __align__(128) __half g_ph [NBQ * NN * CI];   // phi   [bq][m][d] fp16
__device__ __align__(128) __half g_gxT[NBQ * CI * NN];   // g^T   [bq][d][m] fp16
__device__ __align__(128) float  g_y  [NBQ * NN * CI];   // attn out [bq][n][d] fp32
__device__ __align__(128) float  g_M  [4 * 1056];        // per-q {sum_y[32], M[32][32]}
__device__ float g_mu[4 * NC];     // d = w_c . mean(y)  (bias cancels in BN)
__device__ float g_rstd[4 * NC];

// ===========================================================================
// PTX helpers (all legal on compute_103)
// ===========================================================================
__device__ __forceinline__ uint32_t smem_to_u32(const void* p) {
    uint32_t a;
    asm("{ .reg .u64 t; cvta.to.shared.u64 t, %1; cvt.u32.u64 %0, t; }" : "=r"(a) : "l"(p));
    return a;
}
__device__ __forceinline__ void cp16(uint32_t s, const void* g) {
    asm volatile("cp.async.cg.shared.global [%0], [%1], 16;" :: "r"(s), "l"(g));
}
#define CP_COMMIT() asm volatile("cp.async.commit_group;" ::: "memory")
#define CP_WAIT(n)  asm volatile("cp.async.wait_group %0;" :: "n"(n) : "memory")

// 2^x on packed f16x2
__device__ __forceinline__ uint32_t ex2h2(uint32_t x) {
    uint32_t r;
    asm("ex2.approx.f16x2 %0, %1;" : "=r"(r) : "r"(x));
    return r;
}

// f32-accum MMA (for P.V)
__device__ __forceinline__ void mma_f16(float& c0, float& c1, float& c2, float& c3,
                                        uint32_t a0, uint32_t a1, uint32_t a2, uint32_t a3,
                                        uint32_t b0, uint32_t b1) {
    asm volatile(
        "mma.sync.aligned.m16n8k16.row.col.f32.f16.f16.f32 "
        "{%0,%1,%2,%3}, {%4,%5,%6,%7}, {%8,%9}, {%0,%1,%2,%3};"
        : "+f"(c0), "+f"(c1), "+f"(c2), "+f"(c3)
        : "r"(a0), "r"(a1), "r"(a2), "r"(a3), "r"(b0), "r"(b1));
}
// f16-accum MMA (for S = theta.phi^T) — D comes out pre-packed for ex2h2
__device__ __forceinline__ void mma_f16h(uint32_t& d0, uint32_t& d1,
                                         uint32_t a0, uint32_t a1, uint32_t a2, uint32_t a3,
                                         uint32_t b0, uint32_t b1) {
    asm volatile(
        "mma.sync.aligned.m16n8k16.row.col.f16.f16.f16.f16 "
        "{%0,%1}, {%2,%3,%4,%5}, {%6,%7}, {%0,%1};"
        : "+r"(d0), "+r"(d1)
        : "r"(a0), "r"(a1), "r"(a2), "r"(a3), "r"(b0), "r"(b1));
}

// ===========================================================================
// Kernel A: projections (split per-matrix; proven R8 version).
// theta pre-scaled by log2(e); g written transposed fp16 [d][m].
// Blocks (y==0, z==0) also zero g_M for this launch (kernel boundary orders
// it before attn's atomics).
// ===========================================================================
__global__ __launch_bounds__(128) void proj_kernel(
    const float* __restrict__ x,
    const float* __restrict__ tw, const float* __restrict__ tb,
    const float* __restrict__ pw, const float* __restrict__ pb,
    const float* __restrict__ gw, const float* __restrict__ gb)
{
    __shared__ __align__(16) float ws[NC * CI];
    __shared__ float bs[CI];

    int tid = threadIdx.x;
    if (blockIdx.y == 0 && blockIdx.z == 0) {
        for (int i = blockIdx.x * 128 + tid; i < 4 * 1056; i += 32 * 128)
            g_M[i] = 0.0f;
    }

    int mat = blockIdx.y;
    const float* W  = (mat == 0) ? tw : ((mat == 1) ? pw : gw);
    const float* Bv = (mat == 0) ? tb : ((mat == 1) ? pb : gb);
    float scale = (mat == 0) ? LOG2E : 1.0f;

    for (int i = tid; i < CI * NC; i += 128) {
        int o = i >> 6, c = i & 63;
        ws[c * CI + o] = W[i] * scale;
    }
    if (tid < CI) bs[tid] = Bv[tid] * scale;
    __syncthreads();

    int bq = blockIdx.z;
    int n  = blockIdx.x * 128 + tid;
    int b  = bq >> 2, q = bq & 3, qr = q >> 1, qc = q & 1;
    int hh = n >> 6, ww = n & 63;

    const float* xp = x + (size_t)b * NC * HW + (qr * 64 + hh) * NW + (qc * 64 + ww);

    float acc[CI];
#pragma unroll
    for (int o = 0; o < CI; o++) acc[o] = bs[o];

    const float4* ws4 = (const float4*)ws;
#pragma unroll 4
    for (int c = 0; c < NC; c++) {
        float xv = xp[c * HW];
#pragma unroll
        for (int o4 = 0; o4 < 8; o4++) {
            float4 w = ws4[c * 8 + o4];
            acc[o4 * 4 + 0] += w.x * xv;
            acc[o4 * 4 + 1] += w.y * xv;
            acc[o4 * 4 + 2] += w.z * xv;
            acc[o4 * 4 + 3] += w.w * xv;
        }
    }

    if (mat == 2) {
        __half* op = g_gxT + (size_t)bq * CI * NN + n;
#pragma unroll
        for (int o = 0; o < CI; o++) op[(size_t)o * NN] = __float2half_rn(acc[o]);
    } else {
        __half* op = ((mat == 0) ? g_th : g_ph) + ((size_t)bq * NN + n) * CI;
#pragma unroll
        for (int o = 0; o < CI; o += 2) {
            __half2 h2 = __floats2half2_rn(acc[o], acc[o + 1]);
            *(__half2*)(op + o) = h2;
        }
    }
}

// ===========================================================================
// Kernel B: fp16 flash attention — R12 mainloop (bit-identical numerics),
// plus fused y-moment accumulation (sum_y, sum y y^T) in the epilogue.
// grid (32, 8), block 128.
// ===========================================================================
#define PH2 20                         // phi row stride in b32 words (16 data + 4 pad)
#define VT2 68                         // v^T row stride in b32 words (64 data + 4 pad)
#define PHI_WORDS (128 * PH2)          // 2560
#define VT_WORDS  (32 * VT2)           // 2176
#define BUF_WORDS (PHI_WORDS + VT_WORDS)  // 4736
#define PHI_BYTES (PHI_WORDS * 4)
#define BUF_BYTES (BUF_WORDS * 4)      // 18944
#define SMEM_TOTAL (2 * BUF_BYTES)     // 37888

__global__ void __launch_bounds__(128, 2) attn_mma_kernel()
{
    extern __shared__ uint32_t smw[];
    uint32_t sb = smem_to_u32(smw);
    int tid = threadIdx.x, wid = tid >> 5, lane = tid & 31;
    int g = lane >> 2, tig = lane & 3;               // row-group, thread-in-group
    int bq = blockIdx.y, qt = blockIdx.x;

    const __half* phg = g_ph  + (size_t)bq * NN * CI;
    const __half* vtg = g_gxT + (size_t)bq * CI * NN;

    // ---- theta A fragments: two 16-row groups (rows qt*128 + wid*32 + grp*16) ----
    uint32_t aS[2][2][4];
#pragma unroll
    for (int grp = 0; grp < 2; grp++) {
        const __half* thp = g_th + ((size_t)bq * NN + qt * 128 + wid * 32 + grp * 16) * CI;
#pragma unroll
        for (int kk = 0; kk < 2; kk++) {
            aS[grp][kk][0] = *(const uint32_t*)(thp + (size_t)g       * CI + (tig + 8 * kk) * 2);
            aS[grp][kk][1] = *(const uint32_t*)(thp + (size_t)(g + 8) * CI + (tig + 8 * kk) * 2);
            aS[grp][kk][2] = *(const uint32_t*)(thp + (size_t)g       * CI + (tig + 4 + 8 * kk) * 2);
            aS[grp][kk][3] = *(const uint32_t*)(thp + (size_t)(g + 8) * CI + (tig + 4 + 8 * kk) * 2);
        }
    }

    // ---- stage helper: tile t -> buffer buf (phi rows + v^T rows), cp.async ----
    auto stage = [&](int t, int buf) {
        uint32_t base = sb + (uint32_t)buf * BUF_BYTES;
        const __half* pg = phg + (size_t)t * 128 * CI;
#pragma unroll
        for (int cc = 0; cc < 4; cc++) {
            int idx = tid + cc * 128;            // 0..511
            int row = idx >> 2, ch = idx & 3;    // phi: 128 rows x 4 chunks of 16B
            cp16(base + (uint32_t)(row * PH2 + ch * 4) * 4u, pg + (size_t)row * CI + ch * 8);
            int d = idx >> 4, kc = idx & 15;     // v^T: 32 rows x 16 chunks of 16B
            cp16(base + PHI_BYTES + (uint32_t)(d * VT2 + kc * 4) * 4u,
                 vtg + (size_t)d * NN + t * 128 + kc * 8);
        }
    };

    stage(0, 0);
    CP_COMMIT();

    float o[2][4][4];
#pragma unroll
    for (int grp = 0; grp < 2; grp++)
#pragma unroll
        for (int d = 0; d < 4; d++)
#pragma unroll
            for (int j = 0; j < 4; j++) o[grp][d][j] = 0.0f;
    float ls[2][2] = {{0.0f, 0.0f}, {0.0f, 0.0f}};

    for (int t = 0; t < NT; t++) {
        int cur = t & 1;
        if (t + 1 < NT) {
            stage(t + 1, cur ^ 1);
            CP_COMMIT();
            CP_WAIT(1);
        } else {
            CP_WAIT(0);
        }
        __syncthreads();

        const uint32_t* psw = smw + (size_t)cur * BUF_WORDS;
        const uint32_t* vtw = psw + PHI_WORDS;

#pragma unroll
        for (int nbp = 0; nbp < 8; nbp++) {
            const uint32_t* prow0 = psw + (nbp * 16 + g) * PH2;
            const uint32_t* prow1 = psw + (nbp * 16 + 8 + g) * PH2;
            uint32_t p00 = prow0[tig], p01 = prow0[tig + 4];
            uint32_t p02 = prow0[tig + 8], p03 = prow0[tig + 12];
            uint32_t p10 = prow1[tig], p11 = prow1[tig + 4];
            uint32_t p12 = prow1[tig + 8], p13 = prow1[tig + 12];

            uint32_t A[2][4];
#pragma unroll
            for (int grp = 0; grp < 2; grp++) {
                uint32_t s0 = 0, s1 = 0;
                mma_f16h(s0, s1, aS[grp][0][0], aS[grp][0][1], aS[grp][0][2], aS[grp][0][3],
                         p00, p01);
                mma_f16h(s0, s1, aS[grp][1][0], aS[grp][1][1], aS[grp][1][2], aS[grp][1][3],
                         p02, p03);
                uint32_t u0 = 0, u1 = 0;
                mma_f16h(u0, u1, aS[grp][0][0], aS[grp][0][1], aS[grp][0][2], aS[grp][0][3],
                         p10, p11);
                mma_f16h(u0, u1, aS[grp][1][0], aS[grp][1][1], aS[grp][1][2], aS[grp][1][3],
                         p12, p13);
                A[grp][0] = ex2h2(s0);
                A[grp][1] = ex2h2(s1);
                A[grp][2] = ex2h2(u0);
                A[grp][3] = ex2h2(u1);
                __half2 hg = __hadd2(*(__half2*)&A[grp][0], *(__half2*)&A[grp][2]);
                __half2 hb = __hadd2(*(__half2*)&A[grp][1], *(__half2*)&A[grp][3]);
                float2 fg = __half22float2(hg);
                float2 fb = __half22float2(hb);
                ls[grp][0] += fg.x + fg.y;
                ls[grp][1] += fb.x + fb.y;
            }
#pragma unroll
            for (int d = 0; d < 4; d++) {
                const uint32_t* v = vtw + (g + 8 * d) * VT2 + nbp * 8;
                uint32_t vb0 = v[tig], vb1 = v[tig + 4];
                mma_f16(o[0][d][0], o[0][d][1], o[0][d][2], o[0][d][3],
                        A[0][0], A[0][1], A[0][2], A[0][3], vb0, vb1);
                mma_f16(o[1][d][0], o[1][d][1], o[1][d][2], o[1][d][3],
                        A[1][0], A[1][1], A[1][2], A[1][3], vb0, vb1);
            }
        }
        __syncthreads();
    }

    // ---- finalize: normalize, write y to gmem AND to smem (stride 33) ----
    float* smY = (float*)smw;             // [128][33] = 16896B (buffer 0, free now)
#pragma unroll
    for (int grp = 0; grp < 2; grp++) {
        float l0 = ls[grp][0], l1 = ls[grp][1];
        l0 += __shfl_xor_sync(0xFFFFFFFFu, l0, 1);
        l0 += __shfl_xor_sync(0xFFFFFFFFu, l0, 2);
        l1 += __shfl_xor_sync(0xFFFFFFFFu, l1, 1);
        l1 += __shfl_xor_sync(0xFFFFFFFFu, l1, 2);
        float inv0 = 1.0f / l0;
        float inv1 = 1.0f / l1;

        int r0 = wid * 32 + grp * 16 + g;          // CTA-local row
        int row0 = qt * 128 + r0;                  // global row
        float* y0 = g_y + ((size_t)bq * NN + row0) * CI;
        float* y1 = y0 + 8 * CI;
#pragma unroll
        for (int j = 0; j < 4; j++) {
            float a0 = o[grp][j][0] * inv0, a1 = o[grp][j][1] * inv0;
            float b0 = o[grp][j][2] * inv1, b1 = o[grp][j][3] * inv1;
            *(float2*)(y0 + j * 8 + 2 * tig) = make_float2(a0, a1);
            *(float2*)(y1 + j * 8 + 2 * tig) = make_float2(b0, b1);
            int col = j * 8 + 2 * tig;
            smY[r0 * 33 + col]       = a0;
            smY[r0 * 33 + col + 1]   = a1;
            smY[(r0 + 8) * 33 + col]     = b0;
            smY[(r0 + 8) * 33 + col + 1] = b1;
        }
    }
    __syncthreads();

    // ---- per-warp moments over 32 rows ----
    {
        float acc[CI];
#pragma unroll
        for (int i = 0; i < CI; i++) acc[i] = 0.0f;
        float s = 0.0f;
        for (int r = 0; r < 32; r++) {
            float v = smY[(wid * 32 + r) * 33 + lane];
            s += v;
#pragma unroll
            for (int i = 0; i < CI; i++)
                acc[i] += __shfl_sync(0xFFFFFFFFu, v, i) * v;
        }
        float* smM4 = (float*)smw + 4352;        // 4 warps x 1024 = 16KB
        float* smS4 = smM4 + 4096;               // 4 x 32
#pragma unroll
        for (int i = 0; i < CI; i++) smM4[wid * 1024 + i * 32 + lane] = acc[i];
        smS4[wid * 32 + lane] = s;
        __syncthreads();

        int q = bq & 3;
        float* Mg = g_M + q * 1056;
        for (int i = tid; i < 1024; i += 128) {
            float tv = smM4[i] + smM4[1024 + i] + smM4[2048 + i] + smM4[3072 + i];
            atomicAdd(Mg + 32 + i, tv);
        }
        if (tid < 32) {
            float tv = smS4[tid] + smS4[32 + tid] + smS4[64 + tid] + smS4[96 + tid];
            atomicAdd(Mg + tid, tv);
        }
    }
}

// ===========================================================================
// Kernel M: per (q,c): d = w.m ; var = (w^T M w)/N - d^2  — lane-parallel.
// grid 4 (quadrant), block 1024 (32 warps; 2 channels per warp)
// ===========================================================================
__global__ __launch_bounds__(1024) void musigma_kernel(const float* __restrict__ w_w)
{
    __shared__ float M[1024];
    __shared__ float sv[32];
    __shared__ float wsm[64 * 33];

    int q = blockIdx.x, tid = threadIdx.x, w = tid >> 5, lane = tid & 31;
    const float* Mg = g_M + q * 1056;

    M[tid & 1023] = Mg[32 + (tid & 1023)];
    if (tid < 32) sv[tid] = Mg[tid];
    for (int i = tid; i < NC * CI; i += 1024) wsm[(i >> 5) * 33 + (i & 31)] = w_w[i];
    __syncthreads();

#pragma unroll
    for (int cc = 0; cc < 2; cc++) {
        int c = w * 2 + cc;
        const float* wc = wsm + c * 33;
        float tj = 0.0f;
#pragma unroll
        for (int i = 0; i < CI; i++) tj += wc[i] * M[i * 32 + lane];
        float qj = tj * wc[lane];
        float dj = wc[lane] * sv[lane];
#pragma unroll
        for (int off = 16; off > 0; off >>= 1) {
            qj += __shfl_xor_sync(0xFFFFFFFFu, qj, off);
            dj += __shfl_xor_sync(0xFFFFFFFFu, dj, off);
        }
        if (lane == 0) {
            float d = dj * (1.0f / 8192.0f);
            float var = qj * (1.0f / 8192.0f) - d * d;
            g_mu[q * NC + c]   = d;
            g_rstd[q * NC + c] = rsqrtf(var + 1e-5f);
        }
    }
}

// ===========================================================================
// Kernel O: fused W-proj + BN + residual + scatter:
// out = (w_c.y_n - d_qc) * rstd_qc * gamma_c + beta_c + x   (bias cancels)
// grid (64 ntiles of 64, 8 bq), block 256 (16 channels per thread)
// ===========================================================================
__global__ __launch_bounds__(256) void outf_kernel(
    const float* __restrict__ x, const float* __restrict__ w_w,
    const float* __restrict__ gamma, const float* __restrict__ beta,
    float* __restrict__ out)
{
    __shared__ __align__(16) float ys[64 * CI];
    __shared__ __align__(16) float wws[NC * CI];
    __shared__ float mus[NC], rss[NC], gas[NC], bes[NC];

    int bq = blockIdx.y, q = bq & 3, b = bq >> 2;
    int n0 = blockIdx.x * 64;
    int tid = threadIdx.x;

    for (int i = tid; i < NC * CI; i += 256) wws[i] = w_w[i];
    {
        const float4* src = (const float4*)(g_y + ((size_t)bq * NN + n0) * CI);
        float4* dst = (float4*)ys;
#pragma unroll
        for (int i = 0; i < 2; i++) dst[tid + i * 256] = src[tid + i * 256];
    }
    if (tid < NC) {
        mus[tid] = g_mu[q * NC + tid];
        rss[tid] = g_rstd[q * NC + tid];
        gas[tid] = gamma[tid];
        bes[tid] = beta[tid];
    }
    __syncthreads();

    int n = tid & 63;
    int cq = tid >> 6;           // 0..3 -> channels cq*16 .. +15

    float yr[CI];
#pragma unroll
    for (int o = 0; o < CI; o++) yr[o] = ys[n * CI + o];

    int nn = n0 + n;
    int hh = nn >> 6, wq = nn & 63;
    int h = (q >> 1) * 64 + hh, wcol = (q & 1) * 64 + wq;
    size_t xbase = ((size_t)b * NC) * HW + (size_t)h * NW + wcol;

    const float4* wws4 = (const float4*)wws;
#pragma unroll 4
    for (int cc = 0; cc < 16; cc++) {
        int c = cq * 16 + cc;
        float a = 0.0f;
#pragma unroll
        for (int o4 = 0; o4 < 8; o4++) {
            float4 w = wws4[c * 8 + o4];
            a += w.x * yr[o4 * 4 + 0] + w.y * yr[o4 * 4 + 1]
               + w.z * yr[o4 * 4 + 2] + w.w * yr[o4 * 4 + 3];
        }
        size_t idx = xbase + (size_t)c * HW;
        out[idx] = (a - mus[c]) * rss[c] * gas[c] + bes[c] + x[idx];
    }
}

// ===========================================================================
// Launch
// ===========================================================================
extern "C" void kernel_launch(void* const* d_in, const int* in_sizes, int n_in,
                              void* d_out, int out_size)
{
    const float* x   = (const float*)d_in[0];
    const float* gw  = (const float*)d_in[1];
    const float* gb  = (const float*)d_in[2];
    const float* tw  = (const float*)d_in[3];
    const float* tb  = (const float*)d_in[4];
    const float* pw  = (const float*)d_in[5];
    const float* pb  = (const float*)d_in[6];
    const float* ww  = (const float*)d_in[7];
    const float* wb  = (const float*)d_in[8];   // cancels in BN; unused
    const float* bng = (const float*)d_in[9];
    const float* bnb = (const float*)d_in[10];
    float* out = (float*)d_out;
    (void)wb;

    cudaFuncSetAttribute(attn_mma_kernel,
                         cudaFuncAttributeMaxDynamicSharedMemorySize, SMEM_TOTAL);

    dim3 gA(32, 3, 8);
    proj_kernel<<<gA, 128>>>(x, tw, tb, pw, pb, gw, gb);

    dim3 gB(32, 8);
    attn_mma_kernel<<<gB, 128, SMEM_TOTAL>>>();

    musigma_kernel<<<4, 1024>>>(ww);

    dim3 gO(64, 8);
    outf_kernel<<<gO, 256>>>(x, ww, bng, bnb, out);
}

// round 16
// speedup vs baseline: 1.3563x; 1.0633x over previous
#include <cuda_runtime.h>
#include <cuda_fp16.h>
#include <cstdint>
#include <math.h>

// Problem constants
#define NB 2
#define NC 64
#define CI 32
#define NH 128
#define NW 128
#define NBQ 8      // b*4+q
#define NN 4096    // 64*64 spatial per quadrant
#define HW (NH*NW)
#define NT 32      // key tiles of 128
#define LOG2E 1.4426950408889634f

// Scratch (static device globals; allocation-free)
__device__ __align__(128) __half g_th [NBQ * NN * CI];   // theta*log2e [bq][n][d] fp16
__device__ __align__(128) __half g_ph [NBQ * NN * CI];   // phi   [bq][m][d] fp16
__device__ __align__(128) __half g_gxT[NBQ * CI * NN];   // g^T   [bq][d][m] fp16
__device__ __align__(128) float  g_y  [NBQ * NN * CI];   // attn out [bq][n][d] fp32
__device__ __align__(128) float  g_M  [4 * 1056];        // per-q {sum_y[32], M[32][32]}
__device__ float g_mu[4 * NC];     // d = w_c . mean(y)  (bias cancels in BN)
__device__ float g_rstd[4 * NC];

// ===========================================================================
// PTX helpers (all legal on compute_103)
// ===========================================================================
__device__ __forceinline__ uint32_t smem_to_u32(const void* p) {
    uint32_t a;
    asm("{ .reg .u64 t; cvta.to.shared.u64 t, %1; cvt.u32.u64 %0, t; }" : "=r"(a) : "l"(p));
    return a;
}
__device__ __forceinline__ void cp16(uint32_t s, const void* g) {
    asm volatile("cp.async.cg.shared.global [%0], [%1], 16;" :: "r"(s), "l"(g));
}
#define CP_COMMIT() asm volatile("cp.async.commit_group;" ::: "memory")
#define CP_WAIT(n)  asm volatile("cp.async.wait_group %0;" :: "n"(n) : "memory")

// pack two f32 -> f16x2 {lo, hi}
__device__ __forceinline__ uint32_t packh2(float lo, float hi) {
    uint32_t r;
    asm("cvt.rn.f16x2.f32 %0, %1, %2;" : "=r"(r) : "f"(hi), "f"(lo));
    return r;
}
// 2^x on packed f16x2
__device__ __forceinline__ uint32_t ex2h2(uint32_t x) {
    uint32_t r;
    asm("ex2.approx.f16x2 %0, %1;" : "=r"(r) : "r"(x));
    return r;
}

// f32-accum MMA
__device__ __forceinline__ void mma_f16(float& c0, float& c1, float& c2, float& c3,
                                        uint32_t a0, uint32_t a1, uint32_t a2, uint32_t a3,
                                        uint32_t b0, uint32_t b1) {
    asm volatile(
        "mma.sync.aligned.m16n8k16.row.col.f32.f16.f16.f32 "
        "{%0,%1,%2,%3}, {%4,%5,%6,%7}, {%8,%9}, {%0,%1,%2,%3};"
        : "+f"(c0), "+f"(c1), "+f"(c2), "+f"(c3)
        : "r"(a0), "r"(a1), "r"(a2), "r"(a3), "r"(b0), "r"(b1));
}
// f16-accum MMA (for S = theta.phi^T) — D comes out pre-packed for ex2h2
__device__ __forceinline__ void mma_f16h(uint32_t& d0, uint32_t& d1,
                                         uint32_t a0, uint32_t a1, uint32_t a2, uint32_t a3,
                                         uint32_t b0, uint32_t b1) {
    asm volatile(
        "mma.sync.aligned.m16n8k16.row.col.f16.f16.f16.f16 "
        "{%0,%1}, {%2,%3,%4,%5}, {%6,%7}, {%0,%1};"
        : "+r"(d0), "+r"(d1)
        : "r"(a0), "r"(a1), "r"(a2), "r"(a3), "r"(b0), "r"(b1));
}

// ===========================================================================
// Kernel A: projections (split per-matrix; proven R8 version).
// theta pre-scaled by log2(e); g written transposed fp16 [d][m].
// Blocks (y==0, z==0) also zero g_M for this launch.
// ===========================================================================
__global__ __launch_bounds__(128) void proj_kernel(
    const float* __restrict__ x,
    const float* __restrict__ tw, const float* __restrict__ tb,
    const float* __restrict__ pw, const float* __restrict__ pb,
    const float* __restrict__ gw, const float* __restrict__ gb)
{
    __shared__ __align__(16) float ws[NC * CI];
    __shared__ float bs[CI];

    int tid = threadIdx.x;
    if (blockIdx.y == 0 && blockIdx.z == 0) {
        for (int i = blockIdx.x * 128 + tid; i < 4 * 1056; i += 32 * 128)
            g_M[i] = 0.0f;
    }

    int mat = blockIdx.y;
    const float* W  = (mat == 0) ? tw : ((mat == 1) ? pw : gw);
    const float* Bv = (mat == 0) ? tb : ((mat == 1) ? pb : gb);
    float scale = (mat == 0) ? LOG2E : 1.0f;

    for (int i = tid; i < CI * NC; i += 128) {
        int o = i >> 6, c = i & 63;
        ws[c * CI + o] = W[i] * scale;
    }
    if (tid < CI) bs[tid] = Bv[tid] * scale;
    __syncthreads();

    int bq = blockIdx.z;
    int n  = blockIdx.x * 128 + tid;
    int b  = bq >> 2, q = bq & 3, qr = q >> 1, qc = q & 1;
    int hh = n >> 6, ww = n & 63;

    const float* xp = x + (size_t)b * NC * HW + (qr * 64 + hh) * NW + (qc * 64 + ww);

    float acc[CI];
#pragma unroll
    for (int o = 0; o < CI; o++) acc[o] = bs[o];

    const float4* ws4 = (const float4*)ws;
#pragma unroll 4
    for (int c = 0; c < NC; c++) {
        float xv = xp[c * HW];
#pragma unroll
        for (int o4 = 0; o4 < 8; o4++) {
            float4 w = ws4[c * 8 + o4];
            acc[o4 * 4 + 0] += w.x * xv;
            acc[o4 * 4 + 1] += w.y * xv;
            acc[o4 * 4 + 2] += w.z * xv;
            acc[o4 * 4 + 3] += w.w * xv;
        }
    }

    if (mat == 2) {
        __half* op = g_gxT + (size_t)bq * CI * NN + n;
#pragma unroll
        for (int o = 0; o < CI; o++) op[(size_t)o * NN] = __float2half_rn(acc[o]);
    } else {
        __half* op = ((mat == 0) ? g_th : g_ph) + ((size_t)bq * NN + n) * CI;
#pragma unroll
        for (int o = 0; o < CI; o += 2) {
            __half2 h2 = __floats2half2_rn(acc[o], acc[o + 1]);
            *(__half2*)(op + o) = h2;
        }
    }
}

// ===========================================================================
// Kernel B: fp16 flash attention — R12 mainloop + fused y-moment accumulation.
// grid (32, 8), block 128.
// ===========================================================================
#define PH2 20                         // phi row stride in b32 words (16 data + 4 pad)
#define VT2 68                         // v^T row stride in b32 words (64 data + 4 pad)
#define PHI_WORDS (128 * PH2)          // 2560
#define VT_WORDS  (32 * VT2)           // 2176
#define BUF_WORDS (PHI_WORDS + VT_WORDS)  // 4736
#define PHI_BYTES (PHI_WORDS * 4)
#define BUF_BYTES (BUF_WORDS * 4)      // 18944
#define SMEM_TOTAL (2 * BUF_BYTES)     // 37888

__global__ void __launch_bounds__(128, 2) attn_mma_kernel()
{
    extern __shared__ uint32_t smw[];
    uint32_t sb = smem_to_u32(smw);
    int tid = threadIdx.x, wid = tid >> 5, lane = tid & 31;
    int g = lane >> 2, tig = lane & 3;               // row-group, thread-in-group
    int bq = blockIdx.y, qt = blockIdx.x;

    const __half* phg = g_ph  + (size_t)bq * NN * CI;
    const __half* vtg = g_gxT + (size_t)bq * CI * NN;

    // ---- theta A fragments: two 16-row groups (rows qt*128 + wid*32 + grp*16) ----
    uint32_t aS[2][2][4];
#pragma unroll
    for (int grp = 0; grp < 2; grp++) {
        const __half* thp = g_th + ((size_t)bq * NN + qt * 128 + wid * 32 + grp * 16) * CI;
#pragma unroll
        for (int kk = 0; kk < 2; kk++) {
            aS[grp][kk][0] = *(const uint32_t*)(thp + (size_t)g       * CI + (tig + 8 * kk) * 2);
            aS[grp][kk][1] = *(const uint32_t*)(thp + (size_t)(g + 8) * CI + (tig + 8 * kk) * 2);
            aS[grp][kk][2] = *(const uint32_t*)(thp + (size_t)g       * CI + (tig + 4 + 8 * kk) * 2);
            aS[grp][kk][3] = *(const uint32_t*)(thp + (size_t)(g + 8) * CI + (tig + 4 + 8 * kk) * 2);
        }
    }

    // ---- stage helper: tile t -> buffer buf (phi rows + v^T rows), cp.async ----
    auto stage = [&](int t, int buf) {
        uint32_t base = sb + (uint32_t)buf * BUF_BYTES;
        const __half* pg = phg + (size_t)t * 128 * CI;
#pragma unroll
        for (int cc = 0; cc < 4; cc++) {
            int idx = tid + cc * 128;            // 0..511
            int row = idx >> 2, ch = idx & 3;    // phi: 128 rows x 4 chunks of 16B
            cp16(base + (uint32_t)(row * PH2 + ch * 4) * 4u, pg + (size_t)row * CI + ch * 8);
            int d = idx >> 4, kc = idx & 15;     // v^T: 32 rows x 16 chunks of 16B
            cp16(base + PHI_BYTES + (uint32_t)(d * VT2 + kc * 4) * 4u,
                 vtg + (size_t)d * NN + t * 128 + kc * 8);
        }
    };

    stage(0, 0);
    CP_COMMIT();

    float o[2][4][4];
#pragma unroll
    for (int grp = 0; grp < 2; grp++)
#pragma unroll
        for (int d = 0; d < 4; d++)
#pragma unroll
            for (int j = 0; j < 4; j++) o[grp][d][j] = 0.0f;
    float ls[2][2] = {{0.0f, 0.0f}, {0.0f, 0.0f}};

    for (int t = 0; t < NT; t++) {
        int cur = t & 1;
        if (t + 1 < NT) {
            stage(t + 1, cur ^ 1);
            CP_COMMIT();
            CP_WAIT(1);
        } else {
            CP_WAIT(0);
        }
        __syncthreads();

        const uint32_t* psw = smw + (size_t)cur * BUF_WORDS;
        const uint32_t* vtw = psw + PHI_WORDS;

#pragma unroll
        for (int nbp = 0; nbp < 8; nbp++) {
            const uint32_t* prow0 = psw + (nbp * 16 + g) * PH2;
            const uint32_t* prow1 = psw + (nbp * 16 + 8 + g) * PH2;
            uint32_t p00 = prow0[tig], p01 = prow0[tig + 4];
            uint32_t p02 = prow0[tig + 8], p03 = prow0[tig + 12];
            uint32_t p10 = prow1[tig], p11 = prow1[tig + 4];
            uint32_t p12 = prow1[tig + 8], p13 = prow1[tig + 12];

            uint32_t A[2][4];
#pragma unroll
            for (int grp = 0; grp < 2; grp++) {
                uint32_t s0 = 0, s1 = 0;
                mma_f16h(s0, s1, aS[grp][0][0], aS[grp][0][1], aS[grp][0][2], aS[grp][0][3],
                         p00, p01);
                mma_f16h(s0, s1, aS[grp][1][0], aS[grp][1][1], aS[grp][1][2], aS[grp][1][3],
                         p02, p03);
                uint32_t u0 = 0, u1 = 0;
                mma_f16h(u0, u1, aS[grp][0][0], aS[grp][0][1], aS[grp][0][2], aS[grp][0][3],
                         p10, p11);
                mma_f16h(u0, u1, aS[grp][1][0], aS[grp][1][1], aS[grp][1][2], aS[grp][1][3],
                         p12, p13);
                A[grp][0] = ex2h2(s0);
                A[grp][1] = ex2h2(s1);
                A[grp][2] = ex2h2(u0);
                A[grp][3] = ex2h2(u1);
                __half2 hg = __hadd2(*(__half2*)&A[grp][0], *(__half2*)&A[grp][2]);
                __half2 hb = __hadd2(*(__half2*)&A[grp][1], *(__half2*)&A[grp][3]);
                float2 fg = __half22float2(hg);
                float2 fb = __half22float2(hb);
                ls[grp][0] += fg.x + fg.y;
                ls[grp][1] += fb.x + fb.y;
            }
#pragma unroll
            for (int d = 0; d < 4; d++) {
                const uint32_t* v = vtw + (g + 8 * d) * VT2 + nbp * 8;
                uint32_t vb0 = v[tig], vb1 = v[tig + 4];
                mma_f16(o[0][d][0], o[0][d][1], o[0][d][2], o[0][d][3],
                        A[0][0], A[0][1], A[0][2], A[0][3], vb0, vb1);
                mma_f16(o[1][d][0], o[1][d][1], o[1][d][2], o[1][d][3],
                        A[1][0], A[1][1], A[1][2], A[1][3], vb0, vb1);
            }
        }
        __syncthreads();
    }

    // ---- finalize: normalize, write y to gmem AND to smem (stride 33) ----
    float* smY = (float*)smw;             // [128][33] (buffer 0, free now)
#pragma unroll
    for (int grp = 0; grp < 2; grp++) {
        float l0 = ls[grp][0], l1 = ls[grp][1];
        l0 += __shfl_xor_sync(0xFFFFFFFFu, l0, 1);
        l0 += __shfl_xor_sync(0xFFFFFFFFu, l0, 2);
        l1 += __shfl_xor_sync(0xFFFFFFFFu, l1, 1);
        l1 += __shfl_xor_sync(0xFFFFFFFFu, l1, 2);
        float inv0 = 1.0f / l0;
        float inv1 = 1.0f / l1;

        int r0 = wid * 32 + grp * 16 + g;          // CTA-local row
        int row0 = qt * 128 + r0;                  // global row
        float* y0 = g_y + ((size_t)bq * NN + row0) * CI;
        float* y1 = y0 + 8 * CI;
#pragma unroll
        for (int j = 0; j < 4; j++) {
            float a0 = o[grp][j][0] * inv0, a1 = o[grp][j][1] * inv0;
            float b0 = o[grp][j][2] * inv1, b1 = o[grp][j][3] * inv1;
            *(float2*)(y0 + j * 8 + 2 * tig) = make_float2(a0, a1);
            *(float2*)(y1 + j * 8 + 2 * tig) = make_float2(b0, b1);
            int col = j * 8 + 2 * tig;
            smY[r0 * 33 + col]       = a0;
            smY[r0 * 33 + col + 1]   = a1;
            smY[(r0 + 8) * 33 + col]     = b0;
            smY[(r0 + 8) * 33 + col + 1] = b1;
        }
    }
    __syncthreads();

    // ---- per-warp moments over 32 rows; atomic-reduce into g_M ----
    {
        float acc[CI];
#pragma unroll
        for (int i = 0; i < CI; i++) acc[i] = 0.0f;
        float s = 0.0f;
        for (int r = 0; r < 32; r++) {
            float v = smY[(wid * 32 + r) * 33 + lane];
            s += v;
#pragma unroll
            for (int i = 0; i < CI; i++)
                acc[i] += __shfl_sync(0xFFFFFFFFu, v, i) * v;
        }
        float* smM4 = (float*)smw + 4352;
        float* smS4 = smM4 + 4096;
#pragma unroll
        for (int i = 0; i < CI; i++) smM4[wid * 1024 + i * 32 + lane] = acc[i];
        smS4[wid * 32 + lane] = s;
        __syncthreads();

        int q = bq & 3;
        float* Mg = g_M + q * 1056;
        for (int i = tid; i < 1024; i += 128) {
            float tv = smM4[i] + smM4[1024 + i] + smM4[2048 + i] + smM4[3072 + i];
            atomicAdd(Mg + 32 + i, tv);
        }
        if (tid < 32) {
            float tv = smS4[tid] + smS4[32 + tid] + smS4[64 + tid] + smS4[96 + tid];
            atomicAdd(Mg + tid, tv);
        }
    }
}

// ===========================================================================
// Kernel M: per (q,c): d = w.m ; var = (w^T M w)/N - d^2  — lane-parallel.
// grid 4, block 1024 (32 warps; 2 channels per warp)
// ===========================================================================
__global__ __launch_bounds__(1024) void musigma_kernel(const float* __restrict__ w_w)
{
    __shared__ float M[1024];
    __shared__ float sv[32];
    __shared__ float wsm[64 * 33];

    int q = blockIdx.x, tid = threadIdx.x, w = tid >> 5, lane = tid & 31;
    const float* Mg = g_M + q * 1056;

    M[tid & 1023] = Mg[32 + (tid & 1023)];
    if (tid < 32) sv[tid] = Mg[tid];
    for (int i = tid; i < NC * CI; i += 1024) wsm[(i >> 5) * 33 + (i & 31)] = w_w[i];
    __syncthreads();

#pragma unroll
    for (int cc = 0; cc < 2; cc++) {
        int c = w * 2 + cc;
        const float* wc = wsm + c * 33;
        float tj = 0.0f;
#pragma unroll
        for (int i = 0; i < CI; i++) tj += wc[i] * M[i * 32 + lane];
        float qj = tj * wc[lane];
        float dj = wc[lane] * sv[lane];
#pragma unroll
        for (int off = 16; off > 0; off >>= 1) {
            qj += __shfl_xor_sync(0xFFFFFFFFu, qj, off);
            dj += __shfl_xor_sync(0xFFFFFFFFu, dj, off);
        }
        if (lane == 0) {
            float d = dj * (1.0f / 8192.0f);
            float var = qj * (1.0f / 8192.0f) - d * d;
            g_mu[q * NC + c]   = d;
            g_rstd[q * NC + c] = rsqrtf(var + 1e-5f);
        }
    }
}

// ===========================================================================
// Kernel O: tensor-core W-proj + BN + residual + scatter.
// D[128n x 64c] = Y(f16 A-frags) @ W^T(f16 B-frags, stride-20 smem),
// epilogue: out = (d - mu_qc)*rstd_qc*gamma_c + beta_c + x.
// grid (32 ntiles, 8 bq), block 128 (4 warps x 32 rows, attn fragment pattern)
// ===========================================================================
#define YS2 36   // y smem row stride in floats (32 data + 4 pad; float4-aligned)

__global__ __launch_bounds__(128) void outf_kernel(
    const float* __restrict__ x, const float* __restrict__ w_w,
    const float* __restrict__ gamma, const float* __restrict__ beta,
    float* __restrict__ out)
{
    __shared__ __align__(16) float ysm[128 * YS2];     // 18432B
    __shared__ uint32_t wsm[64 * 20];                  // W f16x2 words, stride 20
    __shared__ float mus[NC], rss[NC], gas[NC], bes[NC];

    int bq = blockIdx.y, q = bq & 3, b = bq >> 2;
    int n0 = blockIdx.x * 128;
    int tid = threadIdx.x, wid = tid >> 5, lane = tid & 31;
    int g = lane >> 2, tig = lane & 3;

    // W fp32 -> f16x2 words: row c, word cw = k elems {2cw, 2cw+1}
    for (int i = tid; i < 1024; i += 128) {
        int r = i >> 4, cw = i & 15;
        wsm[r * 20 + cw] = packh2(w_w[r * 32 + 2 * cw], w_w[r * 32 + 2 * cw + 1]);
    }
    // y tile: 1024 float4s
    {
        const float4* src = (const float4*)(g_y + ((size_t)bq * NN + n0) * CI);
        for (int i = tid; i < 1024; i += 128) {
            int row = i >> 3, ch = i & 7;
            *(float4*)(ysm + row * YS2 + ch * 4) = src[i];
        }
    }
    if (tid < NC) {
        mus[tid] = g_mu[q * NC + tid];
        rss[tid] = g_rstd[q * NC + tid];
        gas[tid] = gamma[tid];
        bes[tid] = beta[tid];
    }
    __syncthreads();

    // ---- A fragments from fp32 y (cvt to f16) ----
    uint32_t aY[2][2][4];
#pragma unroll
    for (int grp = 0; grp < 2; grp++) {
        const float* r0 = ysm + (wid * 32 + grp * 16 + g) * YS2;
        const float* r1 = r0 + 8 * YS2;
#pragma unroll
        for (int kk = 0; kk < 2; kk++) {
            int k0 = 2 * tig + 16 * kk;
            aY[grp][kk][0] = packh2(r0[k0], r0[k0 + 1]);
            aY[grp][kk][1] = packh2(r1[k0], r1[k0 + 1]);
            aY[grp][kk][2] = packh2(r0[k0 + 8], r0[k0 + 9]);
            aY[grp][kk][3] = packh2(r1[k0 + 8], r1[k0 + 9]);
        }
    }

    // ---- per-grp x base addresses (rows n0 + wid*32 + grp*16 + g, +8) ----
    size_t xbase[2][2];
#pragma unroll
    for (int grp = 0; grp < 2; grp++) {
#pragma unroll
        for (int half = 0; half < 2; half++) {
            int nn = n0 + wid * 32 + grp * 16 + g + half * 8;
            int hh = nn >> 6, wq = nn & 63;
            int h = (q >> 1) * 64 + hh, wcol = (q & 1) * 64 + wq;
            xbase[grp][half] = ((size_t)b * NC) * HW + (size_t)h * NW + wcol;
        }
    }

    // ---- 8 c-blocks: MMA + fused epilogue ----
#pragma unroll
    for (int cb = 0; cb < 8; cb++) {
        const uint32_t* wrow = wsm + (cb * 8 + g) * 20;
        uint32_t b00 = wrow[tig], b01 = wrow[tig + 4];
        uint32_t b10 = wrow[tig + 8], b11 = wrow[tig + 12];

        int c0 = cb * 8 + 2 * tig, c1 = c0 + 1;
        float m0 = mus[c0], m1 = mus[c1];
        float r0s = rss[c0] * gas[c0], r1s = rss[c1] * gas[c1];
        float be0 = bes[c0], be1 = bes[c1];

#pragma unroll
        for (int grp = 0; grp < 2; grp++) {
            float d0 = 0, d1 = 0, d2 = 0, d3 = 0;
            mma_f16(d0, d1, d2, d3, aY[grp][0][0], aY[grp][0][1], aY[grp][0][2], aY[grp][0][3],
                    b00, b01);
            mma_f16(d0, d1, d2, d3, aY[grp][1][0], aY[grp][1][1], aY[grp][1][2], aY[grp][1][3],
                    b10, b11);
            size_t iA0 = xbase[grp][0] + (size_t)c0 * HW;
            size_t iA1 = xbase[grp][0] + (size_t)c1 * HW;
            size_t iB0 = xbase[grp][1] + (size_t)c0 * HW;
            size_t iB1 = xbase[grp][1] + (size_t)c1 * HW;
            out[iA0] = (d0 - m0) * r0s + be0 + x[iA0];
            out[iA1] = (d1 - m1) * r1s + be1 + x[iA1];
            out[iB0] = (d2 - m0) * r0s + be0 + x[iB0];
            out[iB1] = (d3 - m1) * r1s + be1 + x[iB1];
        }
    }
}

// ===========================================================================
// Launch
// ===========================================================================
extern "C" void kernel_launch(void* const* d_in, const int* in_sizes, int n_in,
                              void* d_out, int out_size)
{
    const float* x   = (const float*)d_in[0];
    const float* gw  = (const float*)d_in[1];
    const float* gb  = (const float*)d_in[2];
    const float* tw  = (const float*)d_in[3];
    const float* tb  = (const float*)d_in[4];
    const float* pw  = (const float*)d_in[5];
    const float* pb  = (const float*)d_in[6];
    const float* ww  = (const float*)d_in[7];
    const float* wb  = (const float*)d_in[8];   // cancels in BN; unused
    const float* bng = (const float*)d_in[9];
    const float* bnb = (const float*)d_in[10];
    float* out = (float*)d_out;
    (void)wb;

    cudaFuncSetAttribute(attn_mma_kernel,
                         cudaFuncAttributeMaxDynamicSharedMemorySize, SMEM_TOTAL);

    dim3 gA(32, 3, 8);
    proj_kernel<<<gA, 128>>>(x, tw, tb, pw, pb, gw, gb);

    dim3 gB(32, 8);
    attn_mma_kernel<<<gB, 128, SMEM_TOTAL>>>();

    musigma_kernel<<<4, 1024>>>(ww);

    dim3 gO(32, 8);
    outf_kernel<<<gO, 128>>>(x, ww, bng, bnb, out);
}

// round 17
// speedup vs baseline: 1.3599x; 1.0026x over previous
#include <cuda_runtime.h>
#include <cuda_fp16.h>
#include <cstdint>
#include <math.h>

// Problem constants
#define NB 2
#define NC 64
#define CI 32
#define NH 128
#define NW 128
#define NBQ 8      // b*4+q
#define NN 4096    // 64*64 spatial per quadrant
#define HW (NH*NW)
#define NT 32      // key tiles of 128
#define LOG2E 1.4426950408889634f

// Scratch (static device globals; allocation-free)
__device__ __align__(128) __half g_th [NBQ * NN * CI];   // theta*log2e [bq][n][d] fp16
__device__ __align__(128) __half g_ph [NBQ * NN * CI];   // phi   [bq][m][d] fp16
__device__ __align__(128) __half g_gxT[NBQ * CI * NN];   // g^T   [bq][d][m] fp16
__device__ __align__(128) float  g_y  [NBQ * NN * CI];   // attn out [bq][n][d] fp32
__device__ __align__(128) float  g_M  [4 * 1056];        // per-q {sum_y[32], M[32][32]}
__device__ float g_mu[4 * NC];     // d = w_c . mean(y)  (bias cancels in BN)
__device__ float g_rstd[4 * NC];

// ===========================================================================
// PTX helpers (all legal on compute_103)
// ===========================================================================
__device__ __forceinline__ uint32_t smem_to_u32(const void* p) {
    uint32_t a;
    asm("{ .reg .u64 t; cvta.to.shared.u64 t, %1; cvt.u32.u64 %0, t; }" : "=r"(a) : "l"(p));
    return a;
}
__device__ __forceinline__ void cp16(uint32_t s, const void* g) {
    asm volatile("cp.async.cg.shared.global [%0], [%1], 16;" :: "r"(s), "l"(g));
}
#define CP_COMMIT() asm volatile("cp.async.commit_group;" ::: "memory")
#define CP_WAIT(n)  asm volatile("cp.async.wait_group %0;" :: "n"(n) : "memory")

// pack two f32 -> f16x2 {lo, hi}
__device__ __forceinline__ uint32_t packh2(float lo, float hi) {
    uint32_t r;
    asm("cvt.rn.f16x2.f32 %0, %1, %2;" : "=r"(r) : "f"(hi), "f"(lo));
    return r;
}
// 2^x on packed f16x2
__device__ __forceinline__ uint32_t ex2h2(uint32_t x) {
    uint32_t r;
    asm("ex2.approx.f16x2 %0, %1;" : "=r"(r) : "r"(x));
    return r;
}

// f32-accum MMA
__device__ __forceinline__ void mma_f16(float& c0, float& c1, float& c2, float& c3,
                                        uint32_t a0, uint32_t a1, uint32_t a2, uint32_t a3,
                                        uint32_t b0, uint32_t b1) {
    asm volatile(
        "mma.sync.aligned.m16n8k16.row.col.f32.f16.f16.f32 "
        "{%0,%1,%2,%3}, {%4,%5,%6,%7}, {%8,%9}, {%0,%1,%2,%3};"
        : "+f"(c0), "+f"(c1), "+f"(c2), "+f"(c3)
        : "r"(a0), "r"(a1), "r"(a2), "r"(a3), "r"(b0), "r"(b1));
}
// f16-accum MMA (for S = theta.phi^T) — D comes out pre-packed for ex2h2
__device__ __forceinline__ void mma_f16h(uint32_t& d0, uint32_t& d1,
                                         uint32_t a0, uint32_t a1, uint32_t a2, uint32_t a3,
                                         uint32_t b0, uint32_t b1) {
    asm volatile(
        "mma.sync.aligned.m16n8k16.row.col.f16.f16.f16.f16 "
        "{%0,%1}, {%2,%3,%4,%5}, {%6,%7}, {%0,%1};"
        : "+r"(d0), "+r"(d1)
        : "r"(a0), "r"(a1), "r"(a2), "r"(a3), "r"(b0), "r"(b1));
}

// ===========================================================================
// Kernel A: projections (split per-matrix; proven R8 version).
// theta pre-scaled by log2(e); g written transposed fp16 [d][m].
// Blocks (y==0, z==0) also zero g_M for this launch.
// ===========================================================================
__global__ __launch_bounds__(128) void proj_kernel(
    const float* __restrict__ x,
    const float* __restrict__ tw, const float* __restrict__ tb,
    const float* __restrict__ pw, const float* __restrict__ pb,
    const float* __restrict__ gw, const float* __restrict__ gb)
{
    __shared__ __align__(16) float ws[NC * CI];
    __shared__ float bs[CI];

    int tid = threadIdx.x;
    if (blockIdx.y == 0 && blockIdx.z == 0) {
        for (int i = blockIdx.x * 128 + tid; i < 4 * 1056; i += 32 * 128)
            g_M[i] = 0.0f;
    }

    int mat = blockIdx.y;
    const float* W  = (mat == 0) ? tw : ((mat == 1) ? pw : gw);
    const float* Bv = (mat == 0) ? tb : ((mat == 1) ? pb : gb);
    float scale = (mat == 0) ? LOG2E : 1.0f;

    for (int i = tid; i < CI * NC; i += 128) {
        int o = i >> 6, c = i & 63;
        ws[c * CI + o] = W[i] * scale;
    }
    if (tid < CI) bs[tid] = Bv[tid] * scale;
    __syncthreads();

    int bq = blockIdx.z;
    int n  = blockIdx.x * 128 + tid;
    int b  = bq >> 2, q = bq & 3, qr = q >> 1, qc = q & 1;
    int hh = n >> 6, ww = n & 63;

    const float* xp = x + (size_t)b * NC * HW + (qr * 64 + hh) * NW + (qc * 64 + ww);

    float acc[CI];
#pragma unroll
    for (int o = 0; o < CI; o++) acc[o] = bs[o];

    const float4* ws4 = (const float4*)ws;
#pragma unroll 4
    for (int c = 0; c < NC; c++) {
        float xv = xp[c * HW];
#pragma unroll
        for (int o4 = 0; o4 < 8; o4++) {
            float4 w = ws4[c * 8 + o4];
            acc[o4 * 4 + 0] += w.x * xv;
            acc[o4 * 4 + 1] += w.y * xv;
            acc[o4 * 4 + 2] += w.z * xv;
            acc[o4 * 4 + 3] += w.w * xv;
        }
    }

    if (mat == 2) {
        __half* op = g_gxT + (size_t)bq * CI * NN + n;
#pragma unroll
        for (int o = 0; o < CI; o++) op[(size_t)o * NN] = __float2half_rn(acc[o]);
    } else {
        __half* op = ((mat == 0) ? g_th : g_ph) + ((size_t)bq * NN + n) * CI;
#pragma unroll
        for (int o = 0; o < CI; o += 2) {
            __half2 h2 = __floats2half2_rn(acc[o], acc[o + 1]);
            *(__half2*)(op + o) = h2;
        }
    }
}

// ===========================================================================
// Kernel B: fp16 flash attention — R12 mainloop + fused y-moment accumulation.
// grid (32, 8), block 128.
// ===========================================================================
#define PH2 20                         // phi row stride in b32 words (16 data + 4 pad)
#define VT2 68                         // v^T row stride in b32 words (64 data + 4 pad)
#define PHI_WORDS (128 * PH2)          // 2560
#define VT_WORDS  (32 * VT2)           // 2176
#define BUF_WORDS (PHI_WORDS + VT_WORDS)  // 4736
#define PHI_BYTES (PHI_WORDS * 4)
#define BUF_BYTES (BUF_WORDS * 4)      // 18944
#define SMEM_TOTAL (2 * BUF_BYTES)     // 37888

__global__ void __launch_bounds__(128, 2) attn_mma_kernel()
{
    extern __shared__ uint32_t smw[];
    uint32_t sb = smem_to_u32(smw);
    int tid = threadIdx.x, wid = tid >> 5, lane = tid & 31;
    int g = lane >> 2, tig = lane & 3;               // row-group, thread-in-group
    int bq = blockIdx.y, qt = blockIdx.x;

    const __half* phg = g_ph  + (size_t)bq * NN * CI;
    const __half* vtg = g_gxT + (size_t)bq * CI * NN;

    // ---- theta A fragments: two 16-row groups (rows qt*128 + wid*32 + grp*16) ----
    uint32_t aS[2][2][4];
#pragma unroll
    for (int grp = 0; grp < 2; grp++) {
        const __half* thp = g_th + ((size_t)bq * NN + qt * 128 + wid * 32 + grp * 16) * CI;
#pragma unroll
        for (int kk = 0; kk < 2; kk++) {
            aS[grp][kk][0] = *(const uint32_t*)(thp + (size_t)g       * CI + (tig + 8 * kk) * 2);
            aS[grp][kk][1] = *(const uint32_t*)(thp + (size_t)(g + 8) * CI + (tig + 8 * kk) * 2);
            aS[grp][kk][2] = *(const uint32_t*)(thp + (size_t)g       * CI + (tig + 4 + 8 * kk) * 2);
            aS[grp][kk][3] = *(const uint32_t*)(thp + (size_t)(g + 8) * CI + (tig + 4 + 8 * kk) * 2);
        }
    }

    // ---- stage helper: tile t -> buffer buf (phi rows + v^T rows), cp.async ----
    auto stage = [&](int t, int buf) {
        uint32_t base = sb + (uint32_t)buf * BUF_BYTES;
        const __half* pg = phg + (size_t)t * 128 * CI;
#pragma unroll
        for (int cc = 0; cc < 4; cc++) {
            int idx = tid + cc * 128;            // 0..511
            int row = idx >> 2, ch = idx & 3;    // phi: 128 rows x 4 chunks of 16B
            cp16(base + (uint32_t)(row * PH2 + ch * 4) * 4u, pg + (size_t)row * CI + ch * 8);
            int d = idx >> 4, kc = idx & 15;     // v^T: 32 rows x 16 chunks of 16B
            cp16(base + PHI_BYTES + (uint32_t)(d * VT2 + kc * 4) * 4u,
                 vtg + (size_t)d * NN + t * 128 + kc * 8);
        }
    };

    stage(0, 0);
    CP_COMMIT();

    float o[2][4][4];
#pragma unroll
    for (int grp = 0; grp < 2; grp++)
#pragma unroll
        for (int d = 0; d < 4; d++)
#pragma unroll
            for (int j = 0; j < 4; j++) o[grp][d][j] = 0.0f;
    float ls[2][2] = {{0.0f, 0.0f}, {0.0f, 0.0f}};

    for (int t = 0; t < NT; t++) {
        int cur = t & 1;
        if (t + 1 < NT) {
            stage(t + 1, cur ^ 1);
            CP_COMMIT();
            CP_WAIT(1);
        } else {
            CP_WAIT(0);
        }
        __syncthreads();

        const uint32_t* psw = smw + (size_t)cur * BUF_WORDS;
        const uint32_t* vtw = psw + PHI_WORDS;

#pragma unroll
        for (int nbp = 0; nbp < 8; nbp++) {
            const uint32_t* prow0 = psw + (nbp * 16 + g) * PH2;
            const uint32_t* prow1 = psw + (nbp * 16 + 8 + g) * PH2;
            uint32_t p00 = prow0[tig], p01 = prow0[tig + 4];
            uint32_t p02 = prow0[tig + 8], p03 = prow0[tig + 12];
            uint32_t p10 = prow1[tig], p11 = prow1[tig + 4];
            uint32_t p12 = prow1[tig + 8], p13 = prow1[tig + 12];

            uint32_t A[2][4];
#pragma unroll
            for (int grp = 0; grp < 2; grp++) {
                uint32_t s0 = 0, s1 = 0;
                mma_f16h(s0, s1, aS[grp][0][0], aS[grp][0][1], aS[grp][0][2], aS[grp][0][3],
                         p00, p01);
                mma_f16h(s0, s1, aS[grp][1][0], aS[grp][1][1], aS[grp][1][2], aS[grp][1][3],
                         p02, p03);
                uint32_t u0 = 0, u1 = 0;
                mma_f16h(u0, u1, aS[grp][0][0], aS[grp][0][1], aS[grp][0][2], aS[grp][0][3],
                         p10, p11);
                mma_f16h(u0, u1, aS[grp][1][0], aS[grp][1][1], aS[grp][1][2], aS[grp][1][3],
                         p12, p13);
                A[grp][0] = ex2h2(s0);
                A[grp][1] = ex2h2(s1);
                A[grp][2] = ex2h2(u0);
                A[grp][3] = ex2h2(u1);
                __half2 hg = __hadd2(*(__half2*)&A[grp][0], *(__half2*)&A[grp][2]);
                __half2 hb = __hadd2(*(__half2*)&A[grp][1], *(__half2*)&A[grp][3]);
                float2 fg = __half22float2(hg);
                float2 fb = __half22float2(hb);
                ls[grp][0] += fg.x + fg.y;
                ls[grp][1] += fb.x + fb.y;
            }
#pragma unroll
            for (int d = 0; d < 4; d++) {
                const uint32_t* v = vtw + (g + 8 * d) * VT2 + nbp * 8;
                uint32_t vb0 = v[tig], vb1 = v[tig + 4];
                mma_f16(o[0][d][0], o[0][d][1], o[0][d][2], o[0][d][3],
                        A[0][0], A[0][1], A[0][2], A[0][3], vb0, vb1);
                mma_f16(o[1][d][0], o[1][d][1], o[1][d][2], o[1][d][3],
                        A[1][0], A[1][1], A[1][2], A[1][3], vb0, vb1);
            }
        }
        __syncthreads();
    }

    // ---- finalize: normalize, write y to gmem AND to smem (stride 33) ----
    float* smY = (float*)smw;             // [128][33] (buffer 0, free now)
#pragma unroll
    for (int grp = 0; grp < 2; grp++) {
        float l0 = ls[grp][0], l1 = ls[grp][1];
        l0 += __shfl_xor_sync(0xFFFFFFFFu, l0, 1);
        l0 += __shfl_xor_sync(0xFFFFFFFFu, l0, 2);
        l1 += __shfl_xor_sync(0xFFFFFFFFu, l1, 1);
        l1 += __shfl_xor_sync(0xFFFFFFFFu, l1, 2);
        float inv0 = 1.0f / l0;
        float inv1 = 1.0f / l1;

        int r0 = wid * 32 + grp * 16 + g;          // CTA-local row
        int row0 = qt * 128 + r0;                  // global row
        float* y0 = g_y + ((size_t)bq * NN + row0) * CI;
        float* y1 = y0 + 8 * CI;
#pragma unroll
        for (int j = 0; j < 4; j++) {
            float a0 = o[grp][j][0] * inv0, a1 = o[grp][j][1] * inv0;
            float b0 = o[grp][j][2] * inv1, b1 = o[grp][j][3] * inv1;
            *(float2*)(y0 + j * 8 + 2 * tig) = make_float2(a0, a1);
            *(float2*)(y1 + j * 8 + 2 * tig) = make_float2(b0, b1);
            int col = j * 8 + 2 * tig;
            smY[r0 * 33 + col]       = a0;
            smY[r0 * 33 + col + 1]   = a1;
            smY[(r0 + 8) * 33 + col]     = b0;
            smY[(r0 + 8) * 33 + col + 1] = b1;
        }
    }
    __syncthreads();

    // ---- per-warp moments over 32 rows; atomic-reduce into g_M ----
    {
        float acc[CI];
#pragma unroll
        for (int i = 0; i < CI; i++) acc[i] = 0.0f;
        float s = 0.0f;
        for (int r = 0; r < 32; r++) {
            float v = smY[(wid * 32 + r) * 33 + lane];
            s += v;
#pragma unroll
            for (int i = 0; i < CI; i++)
                acc[i] += __shfl_sync(0xFFFFFFFFu, v, i) * v;
        }
        float* smM4 = (float*)smw + 4352;
        float* smS4 = smM4 + 4096;
#pragma unroll
        for (int i = 0; i < CI; i++) smM4[wid * 1024 + i * 32 + lane] = acc[i];
        smS4[wid * 32 + lane] = s;
        __syncthreads();

        int q = bq & 3;
        float* Mg = g_M + q * 1056;
        for (int i = tid; i < 1024; i += 128) {
            float tv = smM4[i] + smM4[1024 + i] + smM4[2048 + i] + smM4[3072 + i];
            atomicAdd(Mg + 32 + i, tv);
        }
        if (tid < 32) {
            float tv = smS4[tid] + smS4[32 + tid] + smS4[64 + tid] + smS4[96 + tid];
            atomicAdd(Mg + tid, tv);
        }
    }
}

// ===========================================================================
// Kernel M: per (q,c): d = w.m ; var = (w^T M w)/N - d^2  — lane-parallel.
// grid 4, block 1024 (32 warps; 2 channels per warp)
// ===========================================================================
__global__ __launch_bounds__(1024) void musigma_kernel(const float* __restrict__ w_w)
{
    __shared__ float M[1024];
    __shared__ float sv[32];
    __shared__ float wsm[64 * 33];

    int q = blockIdx.x, tid = threadIdx.x, w = tid >> 5, lane = tid & 31;
    const float* Mg = g_M + q * 1056;

    M[tid & 1023] = Mg[32 + (tid & 1023)];
    if (tid < 32) sv[tid] = Mg[tid];
    for (int i = tid; i < NC * CI; i += 1024) wsm[(i >> 5) * 33 + (i & 31)] = w_w[i];
    __syncthreads();

#pragma unroll
    for (int cc = 0; cc < 2; cc++) {
        int c = w * 2 + cc;
        const float* wc = wsm + c * 33;
        float tj = 0.0f;
#pragma unroll
        for (int i = 0; i < CI; i++) tj += wc[i] * M[i * 32 + lane];
        float qj = tj * wc[lane];
        float dj = wc[lane] * sv[lane];
#pragma unroll
        for (int off = 16; off > 0; off >>= 1) {
            qj += __shfl_xor_sync(0xFFFFFFFFu, qj, off);
            dj += __shfl_xor_sync(0xFFFFFFFFu, dj, off);
        }
        if (lane == 0) {
            float d = dj * (1.0f / 8192.0f);
            float var = qj * (1.0f / 8192.0f) - d * d;
            g_mu[q * NC + c]   = d;
            g_rstd[q * NC + c] = rsqrtf(var + 1e-5f);
        }
    }
}

// ===========================================================================
// Kernel O: tensor-core W-proj + BN + residual + scatter — 64-row tiles.
// grid (64 ntiles, 8 bq), block 128 (4 warps x 16 rows) -> 512 CTAs.
// ===========================================================================
#define YS2 36   // y smem row stride in floats (32 data + 4 pad; float4-aligned)

__global__ __launch_bounds__(128) void outf_kernel(
    const float* __restrict__ x, const float* __restrict__ w_w,
    const float* __restrict__ gamma, const float* __restrict__ beta,
    float* __restrict__ out)
{
    __shared__ __align__(16) float ysm[64 * YS2];      // 9216B
    __shared__ uint32_t wsm[64 * 20];                  // W f16x2 words, stride 20
    __shared__ float mus[NC], rss[NC], gas[NC], bes[NC];

    int bq = blockIdx.y, q = bq & 3, b = bq >> 2;
    int n0 = blockIdx.x * 64;
    int tid = threadIdx.x, wid = tid >> 5, lane = tid & 31;
    int g = lane >> 2, tig = lane & 3;

    // W fp32 -> f16x2 words: row c, word cw = k elems {2cw, 2cw+1}
    for (int i = tid; i < 1024; i += 128) {
        int r = i >> 4, cw = i & 15;
        wsm[r * 20 + cw] = packh2(w_w[r * 32 + 2 * cw], w_w[r * 32 + 2 * cw + 1]);
    }
    // y tile: 512 float4s
    {
        const float4* src = (const float4*)(g_y + ((size_t)bq * NN + n0) * CI);
        for (int i = tid; i < 512; i += 128) {
            int row = i >> 3, ch = i & 7;
            *(float4*)(ysm + row * YS2 + ch * 4) = src[i];
        }
    }
    if (tid < NC) {
        mus[tid] = g_mu[q * NC + tid];
        rss[tid] = g_rstd[q * NC + tid];
        gas[tid] = gamma[tid];
        bes[tid] = beta[tid];
    }
    __syncthreads();

    // ---- A fragments from fp32 y (cvt to f16): one 16-row group per warp ----
    uint32_t aY[2][4];
    {
        const float* r0 = ysm + (wid * 16 + g) * YS2;
        const float* r1 = r0 + 8 * YS2;
#pragma unroll
        for (int kk = 0; kk < 2; kk++) {
            int k0 = 2 * tig + 16 * kk;
            aY[kk][0] = packh2(r0[k0], r0[k0 + 1]);
            aY[kk][1] = packh2(r1[k0], r1[k0 + 1]);
            aY[kk][2] = packh2(r0[k0 + 8], r0[k0 + 9]);
            aY[kk][3] = packh2(r1[k0 + 8], r1[k0 + 9]);
        }
    }

    // ---- x base addresses (rows n0 + wid*16 + g, +8) ----
    size_t xbase[2];
#pragma unroll
    for (int half = 0; half < 2; half++) {
        int nn = n0 + wid * 16 + g + half * 8;
        int hh = nn >> 6, wq = nn & 63;
        int h = (q >> 1) * 64 + hh, wcol = (q & 1) * 64 + wq;
        xbase[half] = ((size_t)b * NC) * HW + (size_t)h * NW + wcol;
    }

    // ---- 8 c-blocks: MMA + fused epilogue ----
#pragma unroll
    for (int cb = 0; cb < 8; cb++) {
        const uint32_t* wrow = wsm + (cb * 8 + g) * 20;
        uint32_t b00 = wrow[tig], b01 = wrow[tig + 4];
        uint32_t b10 = wrow[tig + 8], b11 = wrow[tig + 12];

        int c0 = cb * 8 + 2 * tig, c1 = c0 + 1;
        float m0 = mus[c0], m1 = mus[c1];
        float r0s = rss[c0] * gas[c0], r1s = rss[c1] * gas[c1];
        float be0 = bes[c0], be1 = bes[c1];

        float d0 = 0, d1 = 0, d2 = 0, d3 = 0;
        mma_f16(d0, d1, d2, d3, aY[0][0], aY[0][1], aY[0][2], aY[0][3], b00, b01);
        mma_f16(d0, d1, d2, d3, aY[1][0], aY[1][1], aY[1][2], aY[1][3], b10, b11);

        size_t iA0 = xbase[0] + (size_t)c0 * HW;
        size_t iA1 = xbase[0] + (size_t)c1 * HW;
        size_t iB0 = xbase[1] + (size_t)c0 * HW;
        size_t iB1 = xbase[1] + (size_t)c1 * HW;
        out[iA0] = (d0 - m0) * r0s + be0 + x[iA0];
        out[iA1] = (d1 - m1) * r1s + be1 + x[iA1];
        out[iB0] = (d2 - m0) * r0s + be0 + x[iB0];
        out[iB1] = (d3 - m1) * r1s + be1 + x[iB1];
    }
}

// ===========================================================================
// Launch
// ===========================================================================
extern "C" void kernel_launch(void* const* d_in, const int* in_sizes, int n_in,
                              void* d_out, int out_size)
{
    const float* x   = (const float*)d_in[0];
    const float* gw  = (const float*)d_in[1];
    const float* gb  = (const float*)d_in[2];
    const float* tw  = (const float*)d_in[3];
    const float* tb  = (const float*)d_in[4];
    const float* pw  = (const float*)d_in[5];
    const float* pb  = (const float*)d_in[6];
    const float* ww  = (const float*)d_in[7];
    const float* wb  = (const float*)d_in[8];   // cancels in BN; unused
    const float* bng = (const float*)d_in[9];
    const float* bnb = (const float*)d_in[10];
    float* out = (float*)d_out;
    (void)wb;

    cudaFuncSetAttribute(attn_mma_kernel,
                         cudaFuncAttributeMaxDynamicSharedMemorySize, SMEM_TOTAL);

    dim3 gA(32, 3, 8);
    proj_kernel<<<gA, 128>>>(x, tw, tb, pw, pb, gw, gb);

    dim3 gB(32, 8);
    attn_mma_kernel<<<gB, 128, SMEM_TOTAL>>>();

    musigma_kernel<<<4, 1024>>>(ww);

    dim3 gO(64, 8);
    outf_kernel<<<gO, 128>>>(x, ww, bng, bnb, out);
}